// round 3
// baseline (speedup 1.0000x reference)
#include <cuda_runtime.h>
#include <cuda_bf16.h>
#include <math_constants.h>

// Greedy CTC decode:
//   index[t] = argmax_v emission[t, v]          (first occurrence on ties)
//   char[t]  = -1 if index==0 ; index-1 if index>1 ; 0 if index==1
//   keep[t]  = (char[t] != char[t-1]) && (char[t] != -1)   (char[-1] := -2)
//
// Output buffer (float32): [0..T) = (float)index, [T..2T) = keep (0.0/1.0).

static constexpr int V = 512;            // num labels
static constexpr int WARPS_PER_BLOCK = 8;

__global__ __launch_bounds__(WARPS_PER_BLOCK * 32)
void ctc_argmax_kernel(const float* __restrict__ em,
                       float* __restrict__ out_index,
                       int T)
{
    const int warp = threadIdx.x >> 5;
    const int lane = threadIdx.x & 31;
    const int row  = blockIdx.x * WARPS_PER_BLOCK + warp;
    if (row >= T) return;

    const float4* __restrict__ p =
        reinterpret_cast<const float4*>(em + (size_t)row * V);

    float best = -CUDART_INF_F;
    int   bidx = 0;

    // 512 floats / warp: lane reads float4 at elements {lane*4 + c*128},
    // c = 0..3. Each warp-load touches 512 contiguous bytes (coalesced),
    // 4 independent loads in flight. Indices ascend within a lane, so
    // strict '>' preserves first-occurrence tie-break.
#pragma unroll
    for (int c = 0; c < 4; ++c) {
        const int e = lane * 4 + c * 128;     // element index of v.x
        float4 v = p[lane + c * 32];
        if (v.x > best) { best = v.x; bidx = e;     }
        if (v.y > best) { best = v.y; bidx = e + 1; }
        if (v.z > best) { best = v.z; bidx = e + 2; }
        if (v.w > best) { best = v.w; bidx = e + 3; }
    }

    // Warp argmax reduce; on equal values take the smaller index
    // (matches jnp.argmax first-occurrence semantics).
#pragma unroll
    for (int off = 16; off; off >>= 1) {
        float om = __shfl_xor_sync(0xFFFFFFFFu, best, off);
        int   oi = __shfl_xor_sync(0xFFFFFFFFu, bidx, off);
        if (om > best || (om == best && oi < bidx)) { best = om; bidx = oi; }
    }

    if (lane == 0) out_index[row] = (float)bidx;
}

__device__ __forceinline__ int ctc_char(int i)
{
    // blank(0) -> -1 ; i>1 -> i-1 ; i==1 -> 0
    return (i == 0) ? -1 : ((i > 1) ? i - 1 : 0);
}

__global__ void ctc_keep_kernel(const float* __restrict__ idxf,
                                float* __restrict__ keep,
                                int T)
{
    const int t = blockIdx.x * blockDim.x + threadIdx.x;
    if (t >= T) return;
    const int c  = ctc_char((int)idxf[t]);
    const int pc = (t == 0) ? -2 : ctc_char((int)idxf[t - 1]);
    keep[t] = (c != pc && c != -1) ? 1.0f : 0.0f;
}

extern "C" void kernel_launch(void* const* d_in, const int* in_sizes, int n_in,
                              void* d_out, int out_size)
{
    const float* em = (const float*)d_in[0];
    const int T = in_sizes[0] / V;           // 65536

    float* out = (float*)d_out;
    float* out_index = out;

    const int grid1 = (T + WARPS_PER_BLOCK - 1) / WARPS_PER_BLOCK;
    ctc_argmax_kernel<<<grid1, WARPS_PER_BLOCK * 32>>>(em, out_index, T);

    if (out_size >= 2 * T) {
        float* out_keep = out + T;
        const int threads = 256;
        ctc_keep_kernel<<<(T + threads - 1) / threads, threads>>>(out_index,
                                                                  out_keep, T);
    }
}

// round 4
// speedup vs baseline: 1.0530x; 1.0530x over previous
#include <cuda_runtime.h>
#include <cuda_bf16.h>
#include <math_constants.h>

// Fused greedy CTC decode:
//   index[t] = argmax_v emission[t, v]  (first occurrence on ties)
//   char[t]  = -1 if index==0 ; index-1 if index>1 ; 0 if index==1
//   keep[t]  = (char[t] != char[t-1]) && (char[t] != -1)   (char[-1] := -2)
// Output buffer (float32): [0..T) = (float)index, [T..2T) = keep (0.0/1.0).
//
// Each block owns 32 consecutive rows (8 warps x 4 rows/warp). Per-row char
// values are staged in smem; one warp redundantly computes the argmax of the
// row preceding the block so keep[] is resolved entirely block-locally.
// Redundant traffic: 1 row per 32 = +3.1% HBM.

static constexpr int V = 512;             // num labels
static constexpr int WARPS = 8;
static constexpr int R = 4;               // rows per warp
static constexpr int ROWS_PER_BLOCK = WARPS * R;   // 32

__device__ __forceinline__ int warp_argmax_row(const float* __restrict__ em,
                                               int row, int lane)
{
    const float4* __restrict__ p =
        reinterpret_cast<const float4*>(em + (size_t)row * V);

    float best = -CUDART_INF_F;
    int   bidx = 0;

    // 512 floats / warp: lane reads float4 at elements {lane*4 + c*128}.
    // Each warp-load is 512 contiguous bytes; 4 independent loads in flight.
    // Indices ascend within a lane, so strict '>' keeps first occurrence.
#pragma unroll
    for (int c = 0; c < 4; ++c) {
        const int e = lane * 4 + c * 128;
        float4 v = p[lane + c * 32];
        if (v.x > best) { best = v.x; bidx = e;     }
        if (v.y > best) { best = v.y; bidx = e + 1; }
        if (v.z > best) { best = v.z; bidx = e + 2; }
        if (v.w > best) { best = v.w; bidx = e + 3; }
    }

    // Warp reduce; on equal values take the smaller index (jnp.argmax).
#pragma unroll
    for (int off = 16; off; off >>= 1) {
        float om = __shfl_xor_sync(0xFFFFFFFFu, best, off);
        int   oi = __shfl_xor_sync(0xFFFFFFFFu, bidx, off);
        if (om > best || (om == best && oi < bidx)) { best = om; bidx = oi; }
    }
    return bidx;    // uniform across the warp
}

__device__ __forceinline__ int ctc_char(int i)
{
    // blank(0) -> -1 ; i>1 -> i-1 ; i==1 -> 0
    return (i == 0) ? -1 : ((i > 1) ? i - 1 : 0);
}

__global__ __launch_bounds__(WARPS * 32)
void ctc_fused_kernel(const float* __restrict__ em,
                      float* __restrict__ out_index,
                      float* __restrict__ out_keep,
                      int T)
{
    __shared__ int ch[ROWS_PER_BLOCK + 1];   // ch[0] = char of row base-1

    const int warp = threadIdx.x >> 5;
    const int lane = threadIdx.x & 31;
    const int base = blockIdx.x * ROWS_PER_BLOCK;

    // Each warp: 4 consecutive rows.
#pragma unroll
    for (int i = 0; i < R; ++i) {
        const int local = warp * R + i;
        const int row   = base + local;
        if (row < T) {
            const int bidx = warp_argmax_row(em, row, lane);
            if (lane == 0) {
                out_index[row]  = (float)bidx;
                ch[1 + local]   = ctc_char(bidx);
            }
        }
    }

    // One warp resolves the block-boundary predecessor.
    if (warp == WARPS - 1) {
        if (base == 0) {
            if (lane == 0) ch[0] = -2;           // char[-1] sentinel
        } else {
            const int bidx = warp_argmax_row(em, base - 1, lane);
            if (lane == 0) ch[0] = ctc_char(bidx);
        }
    }
    __syncthreads();

    if (threadIdx.x < ROWS_PER_BLOCK) {
        const int t = base + threadIdx.x;
        if (t < T) {
            const int c  = ch[threadIdx.x + 1];
            const int pc = ch[threadIdx.x];
            out_keep[t] = (c != pc && c != -1) ? 1.0f : 0.0f;
        }
    }
}

extern "C" void kernel_launch(void* const* d_in, const int* in_sizes, int n_in,
                              void* d_out, int out_size)
{
    const float* em = (const float*)d_in[0];
    const int T = in_sizes[0] / V;           // 65536

    float* out       = (float*)d_out;
    float* out_index = out;
    float* out_keep  = out + T;

    const int grid = (T + ROWS_PER_BLOCK - 1) / ROWS_PER_BLOCK;
    ctc_fused_kernel<<<grid, WARPS * 32>>>(em, out_index, out_keep, T);
}